// round 9
// baseline (speedup 1.0000x reference)
#include <cuda_runtime.h>
#include <cstdint>

#define MAXN 50000
#define MAXE 600064
#define F 128
#define LN_EPS 1e-5f

// ---------------- scratch (device globals; no allocation allowed) ----------
__device__ int   g_src[MAXE];
__device__ int   g_dst[MAXE];
__device__ float g_dinv[MAXN];
__device__ int   g_degi[MAXN];
__device__ int   g_off[MAXN + 1];
__device__ int   g_cur[MAXN];
__device__ int2  g_ew[MAXE];      // packed {src, weight bits}
__device__ float g_h[MAXN * F];
__device__ float g_h2[MAXN * F];
__device__ int   g_bsum[16];

// -------- convert edges (dtype-probing) + degree count, ILP-4 ---------------
// degi must be zeroed beforehand. int64 ids are < N; int32 pairs read as u64
// are almost surely >= 2^32, so a 32-entry probe disambiguates.
__global__ void k_convert_count(const void* __restrict__ ei_raw, int N, int E) {
    __shared__ int s_is64;
    if (threadIdx.x == 0) {
        const unsigned long long* p = (const unsigned long long*)ei_raw;
        unsigned long long mx = 0;
#pragma unroll
        for (int i = 0; i < 32; i++) mx = mx > p[i] ? mx : p[i];
        s_is64 = (mx < (unsigned long long)N);
    }
    __syncthreads();
    int e0 = (blockIdx.x * blockDim.x + threadIdx.x) * 4;
    if (e0 >= E) return;
    int m = E - e0; if (m > 4) m = 4;

    int s[4], d[4];
    if (s_is64) {
        const long long* p = (const long long*)ei_raw;
#pragma unroll
        for (int j = 0; j < 4; j++)
            if (j < m) { s[j] = (int)p[e0 + j]; d[j] = (int)p[E + e0 + j]; }
    } else {
        const int* p = (const int*)ei_raw;
#pragma unroll
        for (int j = 0; j < 4; j++)
            if (j < m) { s[j] = p[e0 + j]; d[j] = p[E + e0 + j]; }
    }
#pragma unroll
    for (int j = 0; j < 4; j++)
        if (j < m) { g_src[e0 + j] = s[j]; g_dst[e0 + j] = d[j]; }
#pragma unroll
    for (int j = 0; j < 4; j++)
        if (j < m) atomicAdd(&g_degi[d[j]], 1);
}

// ---------------- scan phase 1: per-block exclusive scan (4096/block) -------
__global__ void __launch_bounds__(1024)
k_scan1(int n) {
    __shared__ int sh[32];
    const int lane = threadIdx.x & 31;
    const int wid  = threadIdx.x >> 5;
    const int i0 = blockIdx.x * 4096 + threadIdx.x * 4;

    int v0 = (i0 + 0 < n) ? g_degi[i0 + 0] : 0;
    int v1 = (i0 + 1 < n) ? g_degi[i0 + 1] : 0;
    int v2 = (i0 + 2 < n) ? g_degi[i0 + 2] : 0;
    int v3 = (i0 + 3 < n) ? g_degi[i0 + 3] : 0;
    int s = v0 + v1 + v2 + v3;

    int x = s;
#pragma unroll
    for (int o = 1; o < 32; o <<= 1) {
        int y = __shfl_up_sync(0xffffffffu, x, o);
        if (lane >= o) x += y;
    }
    if (lane == 31) sh[wid] = x;
    __syncthreads();
    if (wid == 0) {
        int t = sh[lane];
#pragma unroll
        for (int o = 1; o < 32; o <<= 1) {
            int y = __shfl_up_sync(0xffffffffu, t, o);
            if (lane >= o) t += y;
        }
        sh[lane] = t;
    }
    __syncthreads();
    int excl = x - s + ((wid == 0) ? 0 : sh[wid - 1]);

    if (i0 + 0 < n) g_off[i0 + 0] = excl;
    if (i0 + 1 < n) g_off[i0 + 1] = excl + v0;
    if (i0 + 2 < n) g_off[i0 + 2] = excl + v0 + v1;
    if (i0 + 3 < n) g_off[i0 + 3] = excl + v0 + v1 + v2;
    if (threadIdx.x == 1023) g_bsum[blockIdx.x] = excl + s;
}

// ------- scan phase 2 (fused): add block offsets, init cur & dinv ------------
__global__ void k_scan3(int n, int nblk) {
    __shared__ int s_boff;
    int grp = (blockIdx.x * blockDim.x) >> 12;   // 4096-element groups
    if (threadIdx.x == 0) {
        int s = 0;
        for (int b = 0; b < grp; b++) s += g_bsum[b];
        s_boff = s;
    }
    __syncthreads();
    int i = blockIdx.x * blockDim.x + threadIdx.x;
    if (i < n) {
        int val = g_off[i] + s_boff;
        g_off[i] = val;
        g_cur[i] = val;
        g_dinv[i] = rsqrtf((float)g_degi[i] + 1.0f);
    }
    if (blockIdx.x == 0 && threadIdx.x == 0) {
        int s = 0;
        for (int b = 0; b < nblk; b++) s += g_bsum[b];
        g_off[n] = s;
    }
}

// ---------------- CSR fill, ILP-4 -------------------------------------------
__global__ void k_fill(int E) {
    int e0 = (blockIdx.x * blockDim.x + threadIdx.x) * 4;
    if (e0 >= E) return;
    int m = E - e0; if (m > 4) m = 4;

    int s[4], d[4]; float w[4]; int pos[4];
#pragma unroll
    for (int j = 0; j < 4; j++)
        if (j < m) { s[j] = g_src[e0 + j]; d[j] = g_dst[e0 + j]; }
#pragma unroll
    for (int j = 0; j < 4; j++)
        if (j < m) w[j] = g_dinv[s[j]] * g_dinv[d[j]];
#pragma unroll
    for (int j = 0; j < 4; j++)
        if (j < m) pos[j] = atomicAdd(&g_cur[d[j]], 1);
#pragma unroll
    for (int j = 0; j < 4; j++)
        if (j < m) g_ew[pos[j]] = make_int2(s[j], __float_as_int(w[j]));
}

// ---------------- SGEMM: H[N,128] = X[N,128] @ W[128,128] ------------------
// FFMA2 (fma.rn.f32x2) path, R5/R8 geometry (8 rows x 4 cols per thread).
// X staged into SMEM DUPLICATED: xs[r][8q..8q+7]=(x0,x0,x1,x1,x2,x2,x3,x3).
// NEW: one LDS.128 supplies the dup pairs for TWO k-steps (float4 at 4*k2),
// with the two f32x2 operands landing in aligned register pairs.
#define GST 256   // floats per SMEM row (128 duplicated k-values * 2)

__global__ void __launch_bounds__(256, 2)
k_gemm128(const float* __restrict__ X, const float* __restrict__ W,
          float* __restrict__ H, int N) {
    extern __shared__ float xs[];   // 64 * GST floats = 64KB

    const int row0 = blockIdx.x * 64;
    const int c  = threadIdx.x & 31;
    const int rg = threadIdx.x >> 5;

    // stage + duplicate
    for (int i = threadIdx.x; i < 64 * 32; i += 256) {
        int r  = i >> 5;
        int k4 = i & 31;
        float4 v = make_float4(0.f, 0.f, 0.f, 0.f);
        int row = row0 + r;
        if (row < N)
            v = ((const float4*)(X + (size_t)row * F))[k4];
        float* p = &xs[r * GST + k4 * 8];
        *(float4*)(p)     = make_float4(v.x, v.x, v.y, v.y);
        *(float4*)(p + 4) = make_float4(v.z, v.z, v.w, v.w);
    }
    __syncthreads();

    unsigned long long acc[8][2];
#pragma unroll
    for (int r = 0; r < 8; r++) { acc[r][0] = 0ULL; acc[r][1] = 0ULL; }

    const float* Wc = W + 4 * c;          // this thread's 4 columns
    const float* xbase = &xs[(rg * 8) * GST];

#pragma unroll 4
    for (int k2 = 0; k2 < 64; k2++) {     // two k-steps per iteration
        const int ka = 2 * k2, kb = 2 * k2 + 1;
        ulonglong2 wa = *(const ulonglong2*)(Wc + ka * F);
        ulonglong2 wb = *(const ulonglong2*)(Wc + kb * F);
#pragma unroll
        for (int r = 0; r < 8; r++) {
            float4 xq = *(const float4*)(xbase + r * GST + 4 * k2);
            unsigned long long xd0, xd1;
            asm("mov.b64 %0, {%1, %2};" : "=l"(xd0) : "f"(xq.x), "f"(xq.y));
            asm("mov.b64 %0, {%1, %2};" : "=l"(xd1) : "f"(xq.z), "f"(xq.w));
            asm("fma.rn.f32x2 %0, %1, %2, %0;" : "+l"(acc[r][0]) : "l"(xd0), "l"(wa.x));
            asm("fma.rn.f32x2 %0, %1, %2, %0;" : "+l"(acc[r][1]) : "l"(xd0), "l"(wa.y));
            asm("fma.rn.f32x2 %0, %1, %2, %0;" : "+l"(acc[r][0]) : "l"(xd1), "l"(wb.x));
            asm("fma.rn.f32x2 %0, %1, %2, %0;" : "+l"(acc[r][1]) : "l"(xd1), "l"(wb.y));
        }
    }

#pragma unroll
    for (int r = 0; r < 8; r++) {
        int row = row0 + rg * 8 + r;
        if (row < N) {
            float o0, o1, o2, o3;
            asm("mov.b64 {%0, %1}, %2;" : "=f"(o0), "=f"(o1) : "l"(acc[r][0]));
            asm("mov.b64 {%0, %1}, %2;" : "=f"(o2), "=f"(o3) : "l"(acc[r][1]));
            ((float4*)(H + (size_t)row * F))[c] = make_float4(o0, o1, o2, o3);
        }
    }
}

// ------- fused gather + self-loop + bias + LayerNorm + ReLU -----------------
__global__ void __launch_bounds__(256)
k_gather_ln(const float* __restrict__ h,
            const float* __restrict__ b, const float* __restrict__ g,
            const float* __restrict__ be, float* __restrict__ out, int N) {
    int warp = (blockIdx.x * blockDim.x + threadIdx.x) >> 5;
    int lane = threadIdx.x & 31;
    if (warp >= N) return;

    const int beg = g_off[warp];
    const int end = g_off[warp + 1];

    float4 acc = make_float4(0.f, 0.f, 0.f, 0.f);

    int e = beg;
    int2 ew_next = make_int2(0, 0);
    if (e < end) ew_next = g_ew[e];
    while (e < end) {
        int   s  = ew_next.x;
        float we = __int_as_float(ew_next.y);
        int en = e + 1;
        if (en < end) ew_next = g_ew[en];
        float4 hv = ((const float4*)(h + (size_t)s * F))[lane];
        acc.x += hv.x * we;
        acc.y += hv.y * we;
        acc.z += hv.z * we;
        acc.w += hv.w * we;
        e = en;
    }

    // self-loop + bias
    float di = g_dinv[warp];
    float sn = di * di;
    float4 hs = ((const float4*)(h + (size_t)warp * F))[lane];
    float4 bv = ((const float4*)b)[lane];
    acc.x += hs.x * sn + bv.x;
    acc.y += hs.y * sn + bv.y;
    acc.z += hs.z * sn + bv.z;
    acc.w += hs.w * sn + bv.w;

    // LayerNorm
    float ssum = acc.x + acc.y + acc.z + acc.w;
#pragma unroll
    for (int o = 16; o; o >>= 1) ssum += __shfl_xor_sync(0xffffffffu, ssum, o);
    float mu = ssum * (1.0f / F);

    float4 dv;
    dv.x = acc.x - mu; dv.y = acc.y - mu; dv.z = acc.z - mu; dv.w = acc.w - mu;
    float ss = dv.x * dv.x + dv.y * dv.y + dv.z * dv.z + dv.w * dv.w;
#pragma unroll
    for (int o = 16; o; o >>= 1) ss += __shfl_xor_sync(0xffffffffu, ss, o);
    float rs = rsqrtf(ss * (1.0f / F) + LN_EPS);

    float4 gv  = ((const float4*)g)[lane];
    float4 bev = ((const float4*)be)[lane];
    float4 o4;
    o4.x = fmaxf(dv.x * rs * gv.x + bev.x, 0.f);
    o4.y = fmaxf(dv.y * rs * gv.y + bev.y, 0.f);
    o4.z = fmaxf(dv.z * rs * gv.z + bev.z, 0.f);
    o4.w = fmaxf(dv.w * rs * gv.w + bev.w, 0.f);
    ((float4*)(out + (size_t)warp * F))[lane] = o4;
}

// ---------------- launch ----------------------------------------------------
extern "C" void kernel_launch(void* const* d_in, const int* in_sizes, int n_in,
                              void* d_out, int out_size) {
    const float* x   = (const float*)d_in[0];
    const void*  ei  = d_in[1];
    const float* W1  = (const float*)d_in[2];
    const float* b1  = (const float*)d_in[3];
    const float* g1  = (const float*)d_in[4];
    const float* be1 = (const float*)d_in[5];
    const float* W2  = (const float*)d_in[6];
    const float* b2  = (const float*)d_in[7];
    const float* g2  = (const float*)d_in[8];
    const float* be2 = (const float*)d_in[9];
    float* out = (float*)d_out;

    const int N = in_sizes[0] / F;
    const int E = in_sizes[1] / 2;

    float *h, *h2;
    int   *degi;
    cudaGetSymbolAddress((void**)&h,    g_h);
    cudaGetSymbolAddress((void**)&h2,   g_h2);
    cudaGetSymbolAddress((void**)&degi, g_degi);

    const int GEMM_SMEM = 64 * GST * (int)sizeof(float);   // 65536
    cudaFuncSetAttribute(k_gemm128,
                         cudaFuncAttributeMaxDynamicSharedMemorySize, GEMM_SMEM);

    const int nbN  = (N + 255) / 256;
    const int nbE4 = ((E + 3) / 4 + 255) / 256;   // ILP-4 edge kernels
    const int nbG  = (N + 63) / 64;
    const int nbW  = (N * 32 + 255) / 256;        // warp per node
    const int nbS  = (N + 4095) / 4096;           // scan phase-1 blocks

    // ---- CSR build (shared by both layers) ----
    cudaMemsetAsync(degi, 0, (size_t)N * sizeof(int));
    k_convert_count<<<nbE4, 256>>>(ei, N, E);
    k_scan1<<<nbS, 1024>>>(N);
    k_scan3<<<nbN, 256>>>(N, nbS);
    k_fill<<<nbE4, 256>>>(E);

    // ---- layer 1 ----
    k_gemm128<<<nbG, 256, GEMM_SMEM>>>(x, W1, h, N);
    k_gather_ln<<<nbW, 256>>>(h, b1, g1, be1, h2, N);

    // ---- layer 2 ----
    k_gemm128<<<nbG, 256, GEMM_SMEM>>>(h2, W2, h, N);
    k_gather_ln<<<nbW, 256>>>(h, b2, g2, be2, out, N);
}

// round 10
// speedup vs baseline: 1.0743x; 1.0743x over previous
#include <cuda_runtime.h>
#include <cstdint>

#define MAXN 50000
#define MAXE 600064
#define F 128
#define LN_EPS 1e-5f

// ---------------- scratch (device globals; no allocation allowed) ----------
__device__ int   g_src[MAXE];
__device__ int   g_dst[MAXE];
__device__ float g_dinv[MAXN];
__device__ int   g_degi[MAXN];
__device__ int   g_off[MAXN + 1];
__device__ int   g_cur[MAXN];
__device__ int2  g_ew[MAXE];      // packed {src, weight bits}
__device__ float g_h[MAXN * F];
__device__ float g_h2[MAXN * F];
__device__ int   g_bsum[16];

// -------- convert edges (dtype-probing) + degree count ----------------------
// degi must be zeroed beforehand. int64 ids are < N; int32 pairs read as u64
// are almost surely >= 2^32, so a 32-entry probe disambiguates.
__global__ void k_convert_count(const void* __restrict__ ei_raw, int N, int E) {
    __shared__ int s_is64;
    if (threadIdx.x == 0) {
        const unsigned long long* p = (const unsigned long long*)ei_raw;
        unsigned long long mx = 0;
#pragma unroll
        for (int i = 0; i < 32; i++) mx = mx > p[i] ? mx : p[i];
        s_is64 = (mx < (unsigned long long)N);
    }
    __syncthreads();
    int e = blockIdx.x * blockDim.x + threadIdx.x;
    if (e >= E) return;
    int s, d;
    if (s_is64) {
        const long long* p = (const long long*)ei_raw;
        s = (int)p[e]; d = (int)p[E + e];
    } else {
        const int* p = (const int*)ei_raw;
        s = p[e]; d = p[E + e];
    }
    g_src[e] = s;
    g_dst[e] = d;
    atomicAdd(&g_degi[d], 1);
}

// ---------------- scan phase 1: per-block exclusive scan (4096/block) -------
__global__ void __launch_bounds__(1024)
k_scan1(int n) {
    __shared__ int sh[32];
    const int lane = threadIdx.x & 31;
    const int wid  = threadIdx.x >> 5;
    const int i0 = blockIdx.x * 4096 + threadIdx.x * 4;

    int v0 = (i0 + 0 < n) ? g_degi[i0 + 0] : 0;
    int v1 = (i0 + 1 < n) ? g_degi[i0 + 1] : 0;
    int v2 = (i0 + 2 < n) ? g_degi[i0 + 2] : 0;
    int v3 = (i0 + 3 < n) ? g_degi[i0 + 3] : 0;
    int s = v0 + v1 + v2 + v3;

    int x = s;
#pragma unroll
    for (int o = 1; o < 32; o <<= 1) {
        int y = __shfl_up_sync(0xffffffffu, x, o);
        if (lane >= o) x += y;
    }
    if (lane == 31) sh[wid] = x;
    __syncthreads();
    if (wid == 0) {
        int t = sh[lane];
#pragma unroll
        for (int o = 1; o < 32; o <<= 1) {
            int y = __shfl_up_sync(0xffffffffu, t, o);
            if (lane >= o) t += y;
        }
        sh[lane] = t;
    }
    __syncthreads();
    int excl = x - s + ((wid == 0) ? 0 : sh[wid - 1]);

    if (i0 + 0 < n) g_off[i0 + 0] = excl;
    if (i0 + 1 < n) g_off[i0 + 1] = excl + v0;
    if (i0 + 2 < n) g_off[i0 + 2] = excl + v0 + v1;
    if (i0 + 3 < n) g_off[i0 + 3] = excl + v0 + v1 + v2;
    if (threadIdx.x == 1023) g_bsum[blockIdx.x] = excl + s;
}

// ------- scan phase 2 (fused): add block offsets, init cur & dinv ------------
__global__ void k_scan3(int n, int nblk) {
    __shared__ int s_boff;
    int grp = (blockIdx.x * blockDim.x) >> 12;   // 4096-element groups
    if (threadIdx.x == 0) {
        int s = 0;
        for (int b = 0; b < grp; b++) s += g_bsum[b];
        s_boff = s;
    }
    __syncthreads();
    int i = blockIdx.x * blockDim.x + threadIdx.x;
    if (i < n) {
        int val = g_off[i] + s_boff;
        g_off[i] = val;
        g_cur[i] = val;
        g_dinv[i] = rsqrtf((float)g_degi[i] + 1.0f);
    }
    if (blockIdx.x == 0 && threadIdx.x == 0) {
        int s = 0;
        for (int b = 0; b < nblk; b++) s += g_bsum[b];
        g_off[n] = s;
    }
}

__global__ void k_fill(int E) {
    int e = blockIdx.x * blockDim.x + threadIdx.x;
    if (e >= E) return;
    int s = g_src[e];
    int d = g_dst[e];
    int pos = atomicAdd(&g_cur[d], 1);
    float w = g_dinv[s] * g_dinv[d];
    g_ew[pos] = make_int2(s, __float_as_int(w));   // one 8B scattered store
}

// ---------------- SGEMM: H[N,128] = X[N,128] @ W[128,128] ------------------
// FFMA2 (fma.rn.f32x2) path: X staged into SMEM with each value DUPLICATED
// (xs[r][2k]=xs[r][2k+1]=x[r][k]) so the broadcast operand is one LDS.64;
// W pairs (w[k][j0],w[k][j1]) come packed naturally from LDG.128.
// 256 threads, 64-row x 128-col tile, 8 rows x 4 cols (=2 f32x2 pairs) per thread.
// (R5/R8-measured geometry — fastest so far; R7 4x8 and R9 LDS.128 both regressed.)
#define GST 256   // floats per SMEM row (128 duplicated k-values * 2)

__global__ void __launch_bounds__(256, 2)
k_gemm128(const float* __restrict__ X, const float* __restrict__ W,
          float* __restrict__ H, int N) {
    extern __shared__ float xs[];   // 64 * GST floats = 64KB

    const int row0 = blockIdx.x * 64;
    const int c  = threadIdx.x & 31;
    const int rg = threadIdx.x >> 5;

    // stage + duplicate
    for (int i = threadIdx.x; i < 64 * 32; i += 256) {
        int r  = i >> 5;
        int k4 = i & 31;
        float4 v = make_float4(0.f, 0.f, 0.f, 0.f);
        int row = row0 + r;
        if (row < N)
            v = ((const float4*)(X + (size_t)row * F))[k4];
        float* p = &xs[r * GST + k4 * 8];
        *(float4*)(p)     = make_float4(v.x, v.x, v.y, v.y);
        *(float4*)(p + 4) = make_float4(v.z, v.z, v.w, v.w);
    }
    __syncthreads();

    unsigned long long acc[8][2];
#pragma unroll
    for (int r = 0; r < 8; r++) { acc[r][0] = 0ULL; acc[r][1] = 0ULL; }

    const float* Wc = W + 4 * c;          // this thread's 4 columns
    const float* xbase = &xs[(rg * 8) * GST];

#pragma unroll 8
    for (int k = 0; k < 128; k++) {
        ulonglong2 w2 = *(const ulonglong2*)(Wc + k * F);   // (wj0,wj1),(wj2,wj3)
#pragma unroll
        for (int r = 0; r < 8; r++) {
            unsigned long long xd =
                *(const unsigned long long*)(xbase + r * GST + 2 * k);  // (x,x)
            asm("fma.rn.f32x2 %0, %1, %2, %0;" : "+l"(acc[r][0]) : "l"(xd), "l"(w2.x));
            asm("fma.rn.f32x2 %0, %1, %2, %0;" : "+l"(acc[r][1]) : "l"(xd), "l"(w2.y));
        }
    }

#pragma unroll
    for (int r = 0; r < 8; r++) {
        int row = row0 + rg * 8 + r;
        if (row < N) {
            float o0, o1, o2, o3;
            asm("mov.b64 {%0, %1}, %2;" : "=f"(o0), "=f"(o1) : "l"(acc[r][0]));
            asm("mov.b64 {%0, %1}, %2;" : "=f"(o2), "=f"(o3) : "l"(acc[r][1]));
            ((float4*)(H + (size_t)row * F))[c] = make_float4(o0, o1, o2, o3);
        }
    }
}

// ------- fused gather + self-loop + bias + LayerNorm + ReLU -----------------
__global__ void __launch_bounds__(256)
k_gather_ln(const float* __restrict__ h,
            const float* __restrict__ b, const float* __restrict__ g,
            const float* __restrict__ be, float* __restrict__ out, int N) {
    int warp = (blockIdx.x * blockDim.x + threadIdx.x) >> 5;
    int lane = threadIdx.x & 31;
    if (warp >= N) return;

    const int beg = g_off[warp];
    const int end = g_off[warp + 1];

    float4 acc = make_float4(0.f, 0.f, 0.f, 0.f);

    int e = beg;
    int2 ew_next = make_int2(0, 0);
    if (e < end) ew_next = g_ew[e];
    while (e < end) {
        int   s  = ew_next.x;
        float we = __int_as_float(ew_next.y);
        int en = e + 1;
        if (en < end) ew_next = g_ew[en];
        float4 hv = ((const float4*)(h + (size_t)s * F))[lane];
        acc.x += hv.x * we;
        acc.y += hv.y * we;
        acc.z += hv.z * we;
        acc.w += hv.w * we;
        e = en;
    }

    // self-loop + bias
    float di = g_dinv[warp];
    float sn = di * di;
    float4 hs = ((const float4*)(h + (size_t)warp * F))[lane];
    float4 bv = ((const float4*)b)[lane];
    acc.x += hs.x * sn + bv.x;
    acc.y += hs.y * sn + bv.y;
    acc.z += hs.z * sn + bv.z;
    acc.w += hs.w * sn + bv.w;

    // LayerNorm
    float ssum = acc.x + acc.y + acc.z + acc.w;
#pragma unroll
    for (int o = 16; o; o >>= 1) ssum += __shfl_xor_sync(0xffffffffu, ssum, o);
    float mu = ssum * (1.0f / F);

    float4 dv;
    dv.x = acc.x - mu; dv.y = acc.y - mu; dv.z = acc.z - mu; dv.w = acc.w - mu;
    float ss = dv.x * dv.x + dv.y * dv.y + dv.z * dv.z + dv.w * dv.w;
#pragma unroll
    for (int o = 16; o; o >>= 1) ss += __shfl_xor_sync(0xffffffffu, ss, o);
    float rs = rsqrtf(ss * (1.0f / F) + LN_EPS);

    float4 gv  = ((const float4*)g)[lane];
    float4 bev = ((const float4*)be)[lane];
    float4 o4;
    o4.x = fmaxf(dv.x * rs * gv.x + bev.x, 0.f);
    o4.y = fmaxf(dv.y * rs * gv.y + bev.y, 0.f);
    o4.z = fmaxf(dv.z * rs * gv.z + bev.z, 0.f);
    o4.w = fmaxf(dv.w * rs * gv.w + bev.w, 0.f);
    ((float4*)(out + (size_t)warp * F))[lane] = o4;
}

// ---------------- launch ----------------------------------------------------
extern "C" void kernel_launch(void* const* d_in, const int* in_sizes, int n_in,
                              void* d_out, int out_size) {
    const float* x   = (const float*)d_in[0];
    const void*  ei  = d_in[1];
    const float* W1  = (const float*)d_in[2];
    const float* b1  = (const float*)d_in[3];
    const float* g1  = (const float*)d_in[4];
    const float* be1 = (const float*)d_in[5];
    const float* W2  = (const float*)d_in[6];
    const float* b2  = (const float*)d_in[7];
    const float* g2  = (const float*)d_in[8];
    const float* be2 = (const float*)d_in[9];
    float* out = (float*)d_out;

    const int N = in_sizes[0] / F;
    const int E = in_sizes[1] / 2;

    float *h, *h2;
    int   *degi;
    cudaGetSymbolAddress((void**)&h,    g_h);
    cudaGetSymbolAddress((void**)&h2,   g_h2);
    cudaGetSymbolAddress((void**)&degi, g_degi);

    const int GEMM_SMEM = 64 * GST * (int)sizeof(float);   // 65536
    cudaFuncSetAttribute(k_gemm128,
                         cudaFuncAttributeMaxDynamicSharedMemorySize, GEMM_SMEM);

    const int nbN = (N + 255) / 256;
    const int nbE = (E + 255) / 256;
    const int nbG = (N + 63) / 64;
    const int nbW = (N * 32 + 255) / 256;     // warp per node
    const int nbS = (N + 4095) / 4096;        // scan phase-1 blocks

    // Side stream + events for CSR/GEMM1 overlap (host-side resources only;
    // created fresh per call — kernel_launch is invoked only a handful of times).
    cudaStream_t s2;
    cudaEvent_t ev_fork, ev_join;
    cudaStreamCreateWithFlags(&s2, cudaStreamNonBlocking);
    cudaEventCreateWithFlags(&ev_fork, cudaEventDisableTiming);
    cudaEventCreateWithFlags(&ev_join, cudaEventDisableTiming);

    // ---- fork: CSR build on s2, concurrent with layer-1 GEMM on stream 0 ----
    cudaEventRecord(ev_fork, 0);
    cudaStreamWaitEvent(s2, ev_fork, 0);

    cudaMemsetAsync(degi, 0, (size_t)N * sizeof(int), s2);
    k_convert_count<<<nbE, 256, 0, s2>>>(ei, N, E);
    k_scan1<<<nbS, 1024, 0, s2>>>(N);
    k_scan3<<<nbN, 256, 0, s2>>>(N, nbS);
    k_fill<<<nbE, 256, 0, s2>>>(E);
    cudaEventRecord(ev_join, s2);

    k_gemm128<<<nbG, 256, GEMM_SMEM>>>(x, W1, h, N);   // stream 0

    // ---- join: gather needs both GEMM1 output and the CSR ----
    cudaStreamWaitEvent(0, ev_join, 0);

    k_gather_ln<<<nbW, 256>>>(h, b1, g1, be1, h2, N);

    // ---- layer 2 (serial chain on stream 0) ----
    k_gemm128<<<nbG, 256, GEMM_SMEM>>>(h2, W2, h, N);
    k_gather_ln<<<nbW, 256>>>(h, b2, g2, be2, out, N);
}